// round 4
// baseline (speedup 1.0000x reference)
#include <cuda_runtime.h>

#define NT 256
#define TSIZE (1u << 19)
#define TMASK (TSIZE - 1u)

// floor(16 * 1.3819^l), l = 0..15 (precomputed in double; matches numpy)
__constant__ unsigned c_res[16] = {16u, 22u, 30u, 42u, 58u, 80u, 111u, 153u,
                                   212u, 294u, 406u, 561u, 775u, 1072u, 1481u, 2047u};

// shared-memory layout (float offsets)
#define OFF_WS1 0            // 32x64
#define OFF_WS2 2048         // 64x20 (17 padded to 20)
#define OFF_WR1 3328         // 32x64
#define OFF_WR2 5376         // 64x64
#define OFF_WR3 9472         // 64x4  (3 padded to 4)
#define OFF_ACT 9728         // 64 features x NT threads
#define SMEM_FLOATS (OFF_ACT + 64 * NT)
#define SMEM_BYTES (SMEM_FLOATS * 4)

__device__ __forceinline__ float sigmoidf_(float x) { return 1.0f / (1.0f + __expf(-x)); }

// Dense layer: KIN inputs read from per-thread smem activations (stride NT),
// J4*4 outputs accumulated in registers. Weights in smem, [KIN][J4*4] row-major,
// all lanes read the same address -> broadcast LDS128.
template <int KIN, int J4>
__device__ __forceinline__ void dense_layer(const float* __restrict__ act,
                                            const float* __restrict__ w,
                                            float* __restrict__ accOut) {
    float acc[J4 * 4];
#pragma unroll
    for (int j = 0; j < J4 * 4; j++) acc[j] = 0.0f;
#pragma unroll 2
    for (int k = 0; k < KIN; k++) {
        float a = act[k * NT];
        const float4* wr = (const float4*)(w + k * (J4 * 4));
#pragma unroll
        for (int j = 0; j < J4; j++) {
            float4 wv = wr[j];
            acc[4 * j + 0] += a * wv.x;
            acc[4 * j + 1] += a * wv.y;
            acc[4 * j + 2] += a * wv.z;
            acc[4 * j + 3] += a * wv.w;
        }
    }
#pragma unroll
    for (int j = 0; j < J4 * 4; j++) accOut[j] = acc[j];
}

extern __shared__ float smem[];

__global__ __launch_bounds__(NT, 2) void nerf_kernel(
    const float* __restrict__ xyz, const float* __restrict__ dir,
    const float* __restrict__ table,
    const float* __restrict__ ws1, const float* __restrict__ ws2,
    const float* __restrict__ wr1, const float* __restrict__ wr2,
    const float* __restrict__ wr3,
    float* __restrict__ out, int N) {
    const int t = threadIdx.x;
    float* s_ws1 = smem + OFF_WS1;
    float* s_ws2 = smem + OFF_WS2;
    float* s_wr1 = smem + OFF_WR1;
    float* s_wr2 = smem + OFF_WR2;
    float* s_wr3 = smem + OFF_WR3;

    for (int i = t; i < 2048; i += NT) { s_ws1[i] = ws1[i]; s_wr1[i] = wr1[i]; }
    for (int i = t; i < 4096; i += NT) s_wr2[i] = wr2[i];
    for (int i = t; i < 1280; i += NT) {
        int r = i / 20, c = i - r * 20;
        s_ws2[i] = (c < 17) ? ws2[r * 17 + c] : 0.0f;
    }
    for (int i = t; i < 256; i += NT) {
        int r = i >> 2, c = i & 3;
        s_wr3[i] = (c < 3) ? wr3[r * 3 + c] : 0.0f;
    }
    __syncthreads();

    const int gid = blockIdx.x * NT + t;
    if (gid >= N) return;

    float* act = smem + OFF_ACT + t;  // per-thread activation column, stride NT

    const float px = xyz[3 * gid + 0];
    const float py = xyz[3 * gid + 1];
    const float pz = xyz[3 * gid + 2];

    // ---- hash-grid encode: dense levels 0..4 ----
#pragma unroll 1
    for (int l = 0; l < 5; l++) {
        unsigned res = c_res[l];
        float fr = (float)res;
        float fx = px * fr, fy = py * fr, fz = pz * fr;
        float bx = floorf(fx), by = floorf(fy), bz = floorf(fz);
        float wx = fx - bx, wy = fy - by, wz = fz - bz;
        unsigned x0 = (unsigned)bx, y0 = (unsigned)by, z0 = (unsigned)bz;
        unsigned s = res + 1u, s2 = s * s;
        unsigned b = x0 + y0 * s + z0 * s2;
        unsigned i0 = b, i1 = b + 1u, i2 = b + s, i3 = b + s + 1u;
        unsigned i4 = b + s2, i5 = b + s2 + 1u, i6 = b + s2 + s, i7 = b + s2 + s + 1u;

        const float2* tb = (const float2*)table + (size_t)l * TSIZE;
        float2 c0 = __ldg(tb + i0), c1 = __ldg(tb + i1), c2 = __ldg(tb + i2), c3 = __ldg(tb + i3);
        float2 c4 = __ldg(tb + i4), c5 = __ldg(tb + i5), c6 = __ldg(tb + i6), c7 = __ldg(tb + i7);

        float ux = 1.0f - wx, uy = 1.0f - wy, uz = 1.0f - wz;
        float w00 = ux * uy, w10 = wx * uy, w01 = ux * wy, w11 = wx * wy;
        float f0 = uz * (c0.x * w00 + c1.x * w10 + c2.x * w01 + c3.x * w11) +
                   wz * (c4.x * w00 + c5.x * w10 + c6.x * w01 + c7.x * w11);
        float f1 = uz * (c0.y * w00 + c1.y * w10 + c2.y * w01 + c3.y * w11) +
                   wz * (c4.y * w00 + c5.y * w10 + c6.y * w01 + c7.y * w11);
        act[(2 * l + 0) * NT] = f0;
        act[(2 * l + 1) * NT] = f1;
    }

    // ---- hash-grid encode: hashed levels 5..15 ----
#pragma unroll 1
    for (int l = 5; l < 16; l++) {
        unsigned res = c_res[l];
        float fr = (float)res;
        float fx = px * fr, fy = py * fr, fz = pz * fr;
        float bx = floorf(fx), by = floorf(fy), bz = floorf(fz);
        float wx = fx - bx, wy = fy - by, wz = fz - bz;
        unsigned x0 = (unsigned)bx, y0 = (unsigned)by, z0 = (unsigned)bz;
        unsigned x1 = x0 + 1u;
        unsigned hy0 = y0 * 2654435761u, hy1 = hy0 + 2654435761u;
        unsigned hz0 = z0 * 805459861u, hz1 = hz0 + 805459861u;
        unsigned i0 = (x0 ^ hy0 ^ hz0) & TMASK;
        unsigned i1 = (x1 ^ hy0 ^ hz0) & TMASK;
        unsigned i2 = (x0 ^ hy1 ^ hz0) & TMASK;
        unsigned i3 = (x1 ^ hy1 ^ hz0) & TMASK;
        unsigned i4 = (x0 ^ hy0 ^ hz1) & TMASK;
        unsigned i5 = (x1 ^ hy0 ^ hz1) & TMASK;
        unsigned i6 = (x0 ^ hy1 ^ hz1) & TMASK;
        unsigned i7 = (x1 ^ hy1 ^ hz1) & TMASK;

        const float2* tb = (const float2*)table + (size_t)l * TSIZE;
        float2 c0 = __ldg(tb + i0), c1 = __ldg(tb + i1), c2 = __ldg(tb + i2), c3 = __ldg(tb + i3);
        float2 c4 = __ldg(tb + i4), c5 = __ldg(tb + i5), c6 = __ldg(tb + i6), c7 = __ldg(tb + i7);

        float ux = 1.0f - wx, uy = 1.0f - wy, uz = 1.0f - wz;
        float w00 = ux * uy, w10 = wx * uy, w01 = ux * wy, w11 = wx * wy;
        float f0 = uz * (c0.x * w00 + c1.x * w10 + c2.x * w01 + c3.x * w11) +
                   wz * (c4.x * w00 + c5.x * w10 + c6.x * w01 + c7.x * w11);
        float f1 = uz * (c0.y * w00 + c1.y * w10 + c2.y * w01 + c3.y * w11) +
                   wz * (c4.y * w00 + c5.y * w10 + c6.y * w01 + c7.y * w11);
        act[(2 * l + 0) * NT] = f0;
        act[(2 * l + 1) * NT] = f1;
    }

    // ---- sigma MLP: 32 -> 64 (relu) -> 17 ----
    float h[64];
    dense_layer<32, 16>(act, s_ws1, h);
#pragma unroll
    for (int j = 0; j < 64; j++) act[j * NT] = fmaxf(h[j], 0.0f);

    float geo[20];
    dense_layer<64, 5>(act, s_ws2, geo);
    float sigma_raw = geo[0];

    // ---- SH deg-4 direction encoding ----
    const float x = dir[3 * gid + 0] * 2.0f - 1.0f;
    const float y = dir[3 * gid + 1] * 2.0f - 1.0f;
    const float z = dir[3 * gid + 2] * 2.0f - 1.0f;
    float x2 = x * x, y2 = y * y, z2 = z * z;
    float xy = x * y, yz = y * z, xz = x * z;
    float sh[16];
    sh[0] = 0.28209479177387814f;
    sh[1] = -0.48860251190291987f * y;
    sh[2] = 0.48860251190291987f * z;
    sh[3] = -0.48860251190291987f * x;
    sh[4] = 1.0925484305920792f * xy;
    sh[5] = -1.0925484305920792f * yz;
    sh[6] = 0.94617469575756f * z2 - 0.31539156525252f;
    sh[7] = -1.0925484305920792f * xz;
    sh[8] = 0.5462742152960396f * (x2 - y2);
    sh[9] = 0.5900435899266435f * y * (-3.0f * x2 + y2);
    sh[10] = 2.890611442640554f * xy * z;
    sh[11] = 0.4570457994644657f * y * (1.0f - 5.0f * z2);
    sh[12] = 0.3731763325901154f * z * (5.0f * z2 - 3.0f);
    sh[13] = 0.4570457994644657f * x * (1.0f - 5.0f * z2);
    sh[14] = 1.445305721320277f * z * (x2 - y2);
    sh[15] = 0.5900435899266435f * x * (-x2 + 3.0f * y2);

#pragma unroll
    for (int j = 0; j < 16; j++) act[j * NT] = sh[j];
#pragma unroll
    for (int j = 0; j < 16; j++) act[(16 + j) * NT] = geo[1 + j];

    // ---- rgb MLP: 32 -> 64 (relu) -> 64 (relu) -> 3 ----
    dense_layer<32, 16>(act, s_wr1, h);
#pragma unroll
    for (int j = 0; j < 64; j++) act[j * NT] = fmaxf(h[j], 0.0f);

    dense_layer<64, 16>(act, s_wr2, h);
#pragma unroll
    for (int j = 0; j < 64; j++) act[j * NT] = fmaxf(h[j], 0.0f);

    float rgb[4];
    dense_layer<64, 1>(act, s_wr3, rgb);

    out[3 * gid + 0] = sigmoidf_(rgb[0]);
    out[3 * gid + 1] = sigmoidf_(rgb[1]);
    out[3 * gid + 2] = sigmoidf_(rgb[2]);
    out[(size_t)3 * N + gid] = fmaxf(sigma_raw, 0.0f);
}

extern "C" void kernel_launch(void* const* d_in, const int* in_sizes, int n_in,
                              void* d_out, int out_size) {
    const float* xyz = (const float*)d_in[0];
    const float* dir = (const float*)d_in[1];
    const float* table = (const float*)d_in[2];
    const float* ws1 = (const float*)d_in[3];
    const float* ws2 = (const float*)d_in[4];
    const float* wr1 = (const float*)d_in[5];
    const float* wr2 = (const float*)d_in[6];
    const float* wr3 = (const float*)d_in[7];
    float* out = (float*)d_out;
    int N = in_sizes[0] / 3;
    (void)n_in; (void)out_size;

    cudaFuncSetAttribute(nerf_kernel, cudaFuncAttributeMaxDynamicSharedMemorySize, SMEM_BYTES);
    int grid = (N + NT - 1) / NT;
    nerf_kernel<<<grid, NT, SMEM_BYTES>>>(xyz, dir, table, ws1, ws2, wr1, wr2, wr3, out, N);
}

// round 5
// speedup vs baseline: 2.1228x; 2.1228x over previous
#include <cuda_runtime.h>

#define NT 256
#define TSIZE (1u << 19)
#define TMASK (TSIZE - 1u)

// floor(16 * 1.3819^l), l = 0..15 (precomputed in double; matches numpy)
__constant__ unsigned c_res[16] = {16u, 22u, 30u, 42u, 58u, 80u, 111u, 153u,
                                   212u, 294u, 406u, 561u, 775u, 1072u, 1481u, 2047u};

// ---- packed weight layout in constant memory (float offsets) ----
// ws1: 32x64  @ 0      (2048)
// ws2: 64x20  @ 2048   (1280)   cols 17..19 zero-padded (row stride 80B, 16B-aligned)
// wr1: 32x64  @ 3328   (2048)
// wr2: 64x64  @ 5376   (4096)
// wr3: 64x4   @ 9472   (256)    col 3 zero-padded
#define CW_WS1 0
#define CW_WS2 2048
#define CW_WR1 3328
#define CW_WR2 5376
#define CW_WR3 9472
#define CW_TOTAL 9728

__constant__ __align__(16) float c_w[CW_TOTAL];
__device__ __align__(16) float g_pack[CW_TOTAL];

// activation scratch: 64 features x NT threads
#define SMEM_FLOATS (64 * NT)
#define SMEM_BYTES (SMEM_FLOATS * 4)

__device__ __forceinline__ float sigmoidf_(float x) { return 1.0f / (1.0f + __expf(-x)); }

__device__ __forceinline__ unsigned long long pack2(float x, float y) {
    unsigned long long r;
    asm("mov.b64 %0, {%1, %2};" : "=l"(r) : "f"(x), "f"(y));
    return r;
}
__device__ __forceinline__ void unpack2(unsigned long long v, float& x, float& y) {
    asm("mov.b64 {%0, %1}, %2;" : "=f"(x), "=f"(y) : "l"(v));
}
// packed dual FMA: d = a * b + d  (two fp32 rn-FMAs, one issue)
__device__ __forceinline__ void ffma2(unsigned long long& d, unsigned long long a,
                                      unsigned long long b) {
    asm("fma.rn.f32x2 %0, %1, %2, %0;" : "+l"(d) : "l"(a), "l"(b));
}

// Dense layer: KIN inputs from per-thread smem activations (stride NT, conflict-free),
// weights from __constant__ (uniform address -> LDCU, separate port, off the L1 crossbar).
// JP2 = number of 16B weight chunks per row (J = 4*JP2 outputs). Accumulates into
// 2*JP2 packed f32x2 pairs via FFMA2.
template <int KIN, int JP2, int WBASE>
__device__ __forceinline__ void dense_c(const float* __restrict__ act,
                                        unsigned long long* __restrict__ acc) {
#pragma unroll
    for (int j = 0; j < 2 * JP2; j++) acc[j] = 0ull;
#pragma unroll 4
    for (int k = 0; k < KIN; k++) {
        float a = act[k * NT];
        unsigned long long a2 = pack2(a, a);
        const ulonglong2* wr = (const ulonglong2*)(c_w + WBASE + k * (4 * JP2));
#pragma unroll
        for (int j = 0; j < JP2; j++) {
            ulonglong2 wv = wr[j];
            ffma2(acc[2 * j + 0], a2, wv.x);
            ffma2(acc[2 * j + 1], a2, wv.y);
        }
    }
}

// repack weights (with zero padding) into one device buffer for the D2D copy into c_w
__global__ void repack_kernel(const float* __restrict__ ws1, const float* __restrict__ ws2,
                              const float* __restrict__ wr1, const float* __restrict__ wr2,
                              const float* __restrict__ wr3) {
    int i = blockIdx.x * blockDim.x + threadIdx.x;
    if (i >= CW_TOTAL) return;
    float v;
    if (i < CW_WS2) {
        v = ws1[i];
    } else if (i < CW_WR1) {
        int j = i - CW_WS2;
        int r = j / 20, c = j - r * 20;
        v = (c < 17) ? ws2[r * 17 + c] : 0.0f;
    } else if (i < CW_WR2) {
        v = wr1[i - CW_WR1];
    } else if (i < CW_WR3) {
        v = wr2[i - CW_WR2];
    } else {
        int j = i - CW_WR3;
        int r = j >> 2, c = j & 3;
        v = (c < 3) ? wr3[r * 3 + c] : 0.0f;
    }
    g_pack[i] = v;
}

extern __shared__ float smem[];

__global__ __launch_bounds__(NT, 2) void nerf_kernel(
    const float* __restrict__ xyz, const float* __restrict__ dir,
    const float* __restrict__ table,
    float* __restrict__ out, int N) {
    const int t = threadIdx.x;
    const int gid = blockIdx.x * NT + t;
    if (gid >= N) return;

    float* act = smem + t;  // per-thread activation column, stride NT

    const float px = xyz[3 * gid + 0];
    const float py = xyz[3 * gid + 1];
    const float pz = xyz[3 * gid + 2];

    // ---- hash-grid encode: dense levels 0..4 ----
#pragma unroll 1
    for (int l = 0; l < 5; l++) {
        unsigned res = c_res[l];
        float fr = (float)res;
        float fx = px * fr, fy = py * fr, fz = pz * fr;
        float bx = floorf(fx), by = floorf(fy), bz = floorf(fz);
        float wx = fx - bx, wy = fy - by, wz = fz - bz;
        unsigned x0 = (unsigned)bx, y0 = (unsigned)by, z0 = (unsigned)bz;
        unsigned s = res + 1u, s2 = s * s;
        unsigned b = x0 + y0 * s + z0 * s2;
        unsigned i0 = b, i1 = b + 1u, i2 = b + s, i3 = b + s + 1u;
        unsigned i4 = b + s2, i5 = b + s2 + 1u, i6 = b + s2 + s, i7 = b + s2 + s + 1u;

        const float2* tb = (const float2*)table + (size_t)l * TSIZE;
        float2 c0 = __ldg(tb + i0), c1 = __ldg(tb + i1), c2 = __ldg(tb + i2), c3 = __ldg(tb + i3);
        float2 c4 = __ldg(tb + i4), c5 = __ldg(tb + i5), c6 = __ldg(tb + i6), c7 = __ldg(tb + i7);

        float ux = 1.0f - wx, uy = 1.0f - wy, uz = 1.0f - wz;
        float w00 = ux * uy, w10 = wx * uy, w01 = ux * wy, w11 = wx * wy;
        float f0 = uz * (c0.x * w00 + c1.x * w10 + c2.x * w01 + c3.x * w11) +
                   wz * (c4.x * w00 + c5.x * w10 + c6.x * w01 + c7.x * w11);
        float f1 = uz * (c0.y * w00 + c1.y * w10 + c2.y * w01 + c3.y * w11) +
                   wz * (c4.y * w00 + c5.y * w10 + c6.y * w01 + c7.y * w11);
        act[(2 * l + 0) * NT] = f0;
        act[(2 * l + 1) * NT] = f1;
    }

    // ---- hash-grid encode: hashed levels 5..15 ----
#pragma unroll 1
    for (int l = 5; l < 16; l++) {
        unsigned res = c_res[l];
        float fr = (float)res;
        float fx = px * fr, fy = py * fr, fz = pz * fr;
        float bx = floorf(fx), by = floorf(fy), bz = floorf(fz);
        float wx = fx - bx, wy = fy - by, wz = fz - bz;
        unsigned x0 = (unsigned)bx, y0 = (unsigned)by, z0 = (unsigned)bz;
        unsigned x1 = x0 + 1u;
        unsigned hy0 = y0 * 2654435761u, hy1 = hy0 + 2654435761u;
        unsigned hz0 = z0 * 805459861u, hz1 = hz0 + 805459861u;
        unsigned i0 = (x0 ^ hy0 ^ hz0) & TMASK;
        unsigned i1 = (x1 ^ hy0 ^ hz0) & TMASK;
        unsigned i2 = (x0 ^ hy1 ^ hz0) & TMASK;
        unsigned i3 = (x1 ^ hy1 ^ hz0) & TMASK;
        unsigned i4 = (x0 ^ hy0 ^ hz1) & TMASK;
        unsigned i5 = (x1 ^ hy0 ^ hz1) & TMASK;
        unsigned i6 = (x0 ^ hy1 ^ hz1) & TMASK;
        unsigned i7 = (x1 ^ hy1 ^ hz1) & TMASK;

        const float2* tb = (const float2*)table + (size_t)l * TSIZE;
        float2 c0 = __ldg(tb + i0), c1 = __ldg(tb + i1), c2 = __ldg(tb + i2), c3 = __ldg(tb + i3);
        float2 c4 = __ldg(tb + i4), c5 = __ldg(tb + i5), c6 = __ldg(tb + i6), c7 = __ldg(tb + i7);

        float ux = 1.0f - wx, uy = 1.0f - wy, uz = 1.0f - wz;
        float w00 = ux * uy, w10 = wx * uy, w01 = ux * wy, w11 = wx * wy;
        float f0 = uz * (c0.x * w00 + c1.x * w10 + c2.x * w01 + c3.x * w11) +
                   wz * (c4.x * w00 + c5.x * w10 + c6.x * w01 + c7.x * w11);
        float f1 = uz * (c0.y * w00 + c1.y * w10 + c2.y * w01 + c3.y * w11) +
                   wz * (c4.y * w00 + c5.y * w10 + c6.y * w01 + c7.y * w11);
        act[(2 * l + 0) * NT] = f0;
        act[(2 * l + 1) * NT] = f1;
    }

    unsigned long long acc[32];

    // ---- sigma MLP: 32 -> 64 (relu) -> 20(17) ----
    dense_c<32, 16, CW_WS1>(act, acc);
#pragma unroll
    for (int j = 0; j < 32; j++) {
        float lo, hi;
        unpack2(acc[j], lo, hi);
        act[(2 * j + 0) * NT] = fmaxf(lo, 0.0f);
        act[(2 * j + 1) * NT] = fmaxf(hi, 0.0f);
    }

    dense_c<64, 5, CW_WS2>(act, acc);
    float geo[20];
#pragma unroll
    for (int j = 0; j < 10; j++) unpack2(acc[j], geo[2 * j], geo[2 * j + 1]);
    float sigma_raw = geo[0];

    // ---- SH deg-4 direction encoding ----
    const float x = dir[3 * gid + 0] * 2.0f - 1.0f;
    const float y = dir[3 * gid + 1] * 2.0f - 1.0f;
    const float z = dir[3 * gid + 2] * 2.0f - 1.0f;
    float x2 = x * x, y2 = y * y, z2 = z * z;
    float xy = x * y, yz = y * z, xz = x * z;
    act[0 * NT] = 0.28209479177387814f;
    act[1 * NT] = -0.48860251190291987f * y;
    act[2 * NT] = 0.48860251190291987f * z;
    act[3 * NT] = -0.48860251190291987f * x;
    act[4 * NT] = 1.0925484305920792f * xy;
    act[5 * NT] = -1.0925484305920792f * yz;
    act[6 * NT] = 0.94617469575756f * z2 - 0.31539156525252f;
    act[7 * NT] = -1.0925484305920792f * xz;
    act[8 * NT] = 0.5462742152960396f * (x2 - y2);
    act[9 * NT] = 0.5900435899266435f * y * (-3.0f * x2 + y2);
    act[10 * NT] = 2.890611442640554f * xy * z;
    act[11 * NT] = 0.4570457994644657f * y * (1.0f - 5.0f * z2);
    act[12 * NT] = 0.3731763325901154f * z * (5.0f * z2 - 3.0f);
    act[13 * NT] = 0.4570457994644657f * x * (1.0f - 5.0f * z2);
    act[14 * NT] = 1.445305721320277f * z * (x2 - y2);
    act[15 * NT] = 0.5900435899266435f * x * (-x2 + 3.0f * y2);
#pragma unroll
    for (int j = 0; j < 16; j++) act[(16 + j) * NT] = geo[1 + j];

    // ---- rgb MLP: 32 -> 64 (relu) -> 64 (relu) -> 4(3) ----
    dense_c<32, 16, CW_WR1>(act, acc);
#pragma unroll
    for (int j = 0; j < 32; j++) {
        float lo, hi;
        unpack2(acc[j], lo, hi);
        act[(2 * j + 0) * NT] = fmaxf(lo, 0.0f);
        act[(2 * j + 1) * NT] = fmaxf(hi, 0.0f);
    }

    dense_c<64, 16, CW_WR2>(act, acc);
#pragma unroll
    for (int j = 0; j < 32; j++) {
        float lo, hi;
        unpack2(acc[j], lo, hi);
        act[(2 * j + 0) * NT] = fmaxf(lo, 0.0f);
        act[(2 * j + 1) * NT] = fmaxf(hi, 0.0f);
    }

    dense_c<64, 1, CW_WR3>(act, acc);
    float r0, r1, r2, r3;
    unpack2(acc[0], r0, r1);
    unpack2(acc[1], r2, r3);

    out[3 * gid + 0] = sigmoidf_(r0);
    out[3 * gid + 1] = sigmoidf_(r1);
    out[3 * gid + 2] = sigmoidf_(r2);
    out[(size_t)3 * N + gid] = fmaxf(sigma_raw, 0.0f);
}

extern "C" void kernel_launch(void* const* d_in, const int* in_sizes, int n_in,
                              void* d_out, int out_size) {
    const float* xyz = (const float*)d_in[0];
    const float* dir = (const float*)d_in[1];
    const float* table = (const float*)d_in[2];
    const float* ws1 = (const float*)d_in[3];
    const float* ws2 = (const float*)d_in[4];
    const float* wr1 = (const float*)d_in[5];
    const float* wr2 = (const float*)d_in[6];
    const float* wr3 = (const float*)d_in[7];
    float* out = (float*)d_out;
    int N = in_sizes[0] / 3;
    (void)n_in; (void)out_size;

    // stage weights: repack (pad) -> device buffer -> constant bank (D2D, capturable)
    repack_kernel<<<(CW_TOTAL + 255) / 256, 256>>>(ws1, ws2, wr1, wr2, wr3);
    void* packed_ptr = nullptr;
    cudaGetSymbolAddress(&packed_ptr, g_pack);
    cudaMemcpyToSymbolAsync(c_w, packed_ptr, CW_TOTAL * sizeof(float), 0,
                            cudaMemcpyDeviceToDevice, 0);

    cudaFuncSetAttribute(nerf_kernel, cudaFuncAttributeMaxDynamicSharedMemorySize, SMEM_BYTES);
    int grid = (N + NT - 1) / NT;
    nerf_kernel<<<grid, NT, SMEM_BYTES>>>(xyz, dir, table, out, N);
}